// round 11
// baseline (speedup 1.0000x reference)
#include <cuda_runtime.h>
#include <cuda_bf16.h>
#include <stdint.h>
#include <math.h>

#define NTOK 32768
#define BATCH 8
#define SEQ 4096
#define DDIM 1024
#define HDIM 2048
#define MAXK 64

#define BM 128
#define BN 256
#define BK 64                        // int8 elements (= bytes) per k-stage
#define NHC 8
#define UNIT_KSTAGES (DDIM / BK)     // 16

// smem: 3 stages of [A 128x80B = 10240][B 256x80B = 20480] = 30720 each
#define STAGE_BYTES 30720
#define NPIPE 3
#define B1S_OFF  (NPIPE * STAGE_BYTES)      // 92160
#define W2S_OFF  (B1S_OFF + 1024)
#define RED_OFF  (W2S_OFF + 1024)
#define DYN_SMEM (RED_OFF + 2048)           // 96256

#define ASCALE 20.0f
#define WSCALE 512.0f
#define INVSC  (1.0f / (20.0f * 512.0f))
#define BANDW  0.24f
#define MAXBAND 128

// ---------------- scratch ----------------
static __device__ float g_part[(size_t)NTOK * NHC];
static __device__ float g_mask[NTOK];
static __device__ int   g_ksel;
static __device__ uint8_t g_Xq[(size_t)NTOK * DDIM];
static __device__ uint8_t g_Wq[(size_t)HDIM * DDIM];   // n-major (transposed)
static __device__ int   g_band_idx[BATCH * MAXBAND];
static __device__ float g_band_partial[BATCH * MAXBAND * 16];
static __device__ int   g_bandcnt[BATCH];
static __device__ int   g_bandsel[BATCH];

// ---------------- PTX helpers ----------------
__device__ __forceinline__ uint32_t smem_u32(const void* p) {
  uint32_t a;
  asm("{ .reg .u64 t; cvta.to.shared.u64 t, %1; cvt.u32.u64 %0, t; }" : "=r"(a) : "l"(p));
  return a;
}
__device__ __forceinline__ void cp16(uint32_t saddr, const void* gaddr) {
  asm volatile("cp.async.cg.shared.global [%0], [%1], 16;" :: "r"(saddr), "l"(gaddr));
}
#define CP_COMMIT() asm volatile("cp.async.commit_group;" ::: "memory")
#define CP_WAIT1()  asm volatile("cp.async.wait_group 1;" ::: "memory")
#define CP_WAIT0()  asm volatile("cp.async.wait_group 0;" ::: "memory")

__device__ __forceinline__ uint32_t lds32(uint32_t addr) {
  uint32_t v;
  asm volatile("ld.shared.b32 %0, [%1];" : "=r"(v) : "r"(addr));
  return v;
}
// s8 mma: D(s32) += A(16x32 s8) * B(32x8 s8)
__device__ __forceinline__ void mma16832(int* c, const uint32_t* a, const uint32_t* b) {
  asm volatile("mma.sync.aligned.m16n8k32.row.col.s32.s8.s8.s32 "
               "{%0,%1,%2,%3}, {%4,%5,%6,%7}, {%8,%9}, {%0,%1,%2,%3};"
               : "+r"(c[0]), "+r"(c[1]), "+r"(c[2]), "+r"(c[3])
               : "r"(a[0]), "r"(a[1]), "r"(a[2]), "r"(a[3]), "r"(b[0]), "r"(b[1]));
}

// ---------------- threefry2x32-20 (JAX) ----------------
__host__ __device__ __forceinline__ void tf2x32(uint32_t k0, uint32_t k1,
                                                uint32_t x0, uint32_t x1,
                                                uint32_t* o0, uint32_t* o1) {
  uint32_t ks2 = k0 ^ k1 ^ 0x1BD11BDAu;
#define ROTL(v, d) (((v) << (d)) | ((v) >> (32 - (d))))
#define RND(r) { x0 += x1; x1 = ROTL(x1, r); x1 ^= x0; }
  x0 += k0; x1 += k1;
  RND(13) RND(15) RND(26) RND(6)
  x0 += k1; x1 += ks2 + 1u;
  RND(17) RND(29) RND(16) RND(24)
  x0 += ks2; x1 += k0 + 2u;
  RND(13) RND(15) RND(26) RND(6)
  x0 += k0; x1 += k1 + 3u;
  RND(17) RND(29) RND(16) RND(24)
  x0 += k1; x1 += ks2 + 4u;
  RND(13) RND(15) RND(26) RND(6)
  x0 += ks2; x1 += k0 + 5u;
#undef RND
#undef ROTL
  *o0 = x0; *o1 = x1;
}
__device__ __forceinline__ float gumbel_at(uint32_t k0, uint32_t k1, uint32_t idx) {
  uint32_t a, b;
  tf2x32(k0, k1, 0u, idx, &a, &b);
  uint32_t bits = a ^ b;
  float u = __uint_as_float((bits >> 9) | 0x3f800000u) - 1.0f;
  u = u + 1e-8f;
  u = fmaxf(1e-8f, u);
  return -logf(-logf(u));
}

// ---------------- quantization kernels ----------------
__device__ __forceinline__ int q8(float x, float s) {
  int q = __float2int_rn(x * s);
  return q < -127 ? -127 : (q > 127 ? 127 : q);
}
__global__ __launch_bounds__(256) void convX_kernel(const float* __restrict__ X) {
  size_t i = (size_t)blockIdx.x * 256 + threadIdx.x;   // float4 index
  float4 v = ((const float4*)X)[i];
  uint32_t p = (uint32_t)(q8(v.x, ASCALE) & 0xFF)
             | ((uint32_t)(q8(v.y, ASCALE) & 0xFF) << 8)
             | ((uint32_t)(q8(v.z, ASCALE) & 0xFF) << 16)
             | ((uint32_t)(q8(v.w, ASCALE) & 0xFF) << 24);
  ((uint32_t*)g_Xq)[i] = p;
}

__global__ __launch_bounds__(256) void convW_kernel(const float* __restrict__ W1) {
  __shared__ float s[32][33];
  int n0 = blockIdx.x * 32;
  int k0 = blockIdx.y * 32;
  int tx = threadIdx.x & 31, ty = threadIdx.x >> 5;
#pragma unroll
  for (int j = 0; j < 4; j++) {
    int k = k0 + ty + j * 8;
    s[ty + j * 8][tx] = W1[(size_t)k * HDIM + n0 + tx];
  }
  __syncthreads();
#pragma unroll
  for (int j = 0; j < 4; j++) {
    int n = n0 + ty + j * 8;
    g_Wq[(size_t)n * DDIM + k0 + tx] = (uint8_t)(int8_t)q8(s[tx][ty + j * 8], WSCALE);
  }
}

// ---------------- k-select ----------------
__global__ void k_select_kernel(const float* __restrict__ k_logits,
                                float* __restrict__ out_ek,
                                uint32_t r1k0, uint32_t r1k1) {
  __shared__ float z[MAXK];
  int t = threadIdx.x;
  if (t < MAXK) z[t] = k_logits[t] + gumbel_at(r1k0, r1k1, (uint32_t)t);
  __syncthreads();
  if (t == 0) {
    float m = -INFINITY; int am = 0;
    for (int i = 0; i < MAXK; i++) if (z[i] > m) { m = z[i]; am = i; }
    float s = 0.0f, e[MAXK];
    for (int i = 0; i < MAXK; i++) { e[i] = expf(z[i] - m); s += e[i]; }
    float ek = 0.0f;
    for (int i = 0; i < MAXK; i++) ek += (e[i] / s) * (float)(i + 1);
    out_ek[0] = ek;
    g_ksel = am + 1;
  }
}

// ---------------- int8 mma GEMM -> per-chunk partial logits ----------------
// grid = 2048 units (256 row-blocks x 8 h-chunks), 512 threads.
// Fragments loaded with plain LDS.32 at PTX-documented s8 mma coordinates.
__global__ __launch_bounds__(512, 1)
void gemm_logits_kernel(const float* __restrict__ b1, const float* __restrict__ W2) {
  extern __shared__ char smem[];
  const uint32_t sb = smem_u32(smem);
  const int tid = threadIdx.x;
  const int lane = tid & 31;
  const int wid = tid >> 5;
  const int wm = wid & 3;           // 0..3 (m, 32-row slices)
  const int wn = wid >> 2;          // 0..3 (n, 64-col slices)
  const int row0 = (blockIdx.x >> 3) * BM;
  const int hc = blockIdx.x & 7;

  float* b1s = (float*)(smem + B1S_OFF);
  float* w2s = (float*)(smem + W2S_OFF);
  float* red = (float*)(smem + RED_OFF);

  // loader: A 512 + B 1024 16B-chunks = 3 per thread
  const int cr = tid >> 2, ch = tid & 3;   // row 0..127, 16B chunk 0..3
  const char* pXb = (const char*)g_Xq + (((size_t)(row0 + cr)) << 10) + ch * 16;
  const char* pWb = (const char*)g_Wq + (((size_t)(hc * BN + cr)) << 10) + ch * 16;
  const uint32_t sA = (uint32_t)(cr * 80 + ch * 16);

#define ISSUE_STAGE(stgbase, ks) do {                                        \
    const uint32_t _stg = (stgbase);                                         \
    const size_t _ko = ((size_t)(ks)) << 6;                                  \
    cp16(_stg + sA,                          pXb + _ko);                     \
    cp16(_stg + 10240 + sA,                  pWb + _ko);                     \
    cp16(_stg + 10240 + sA + 128 * 80,       pWb + (128ull << 10) + _ko);    \
  } while (0)

  ISSUE_STAGE(sb, 0);
  CP_COMMIT();
  ISSUE_STAGE(sb + STAGE_BYTES, 1);
  CP_COMMIT();

  if (tid < 256) {
    b1s[tid] = b1[hc * BN + tid];
    w2s[tid] = W2[hc * BN + tid];
  }

  int C[2][8][4];
#pragma unroll
  for (int mi = 0; mi < 2; mi++)
#pragma unroll
    for (int ni = 0; ni < 8; ni++)
#pragma unroll
      for (int j = 0; j < 4; j++) C[mi][ni][j] = 0;

  const int lr = lane >> 2;              // 0..7
  const uint32_t lc4 = (uint32_t)((lane & 3) * 4);
  const uint32_t aRowOff = (uint32_t)((wm * 32 + lr) * 80);
  const uint32_t bRowOff = (uint32_t)(10240 + (wn * 64 + lr) * 80);

  int buf = 0;
  for (int s = 0; s < UNIT_KSTAGES; s++) {
    if (s + 2 < UNIT_KSTAGES) CP_WAIT1(); else CP_WAIT0();
    __syncthreads();
    if (s + 2 < UNIT_KSTAGES) {
      int b2i = buf + 2; if (b2i >= NPIPE) b2i -= NPIPE;
      ISSUE_STAGE(sb + b2i * STAGE_BYTES, s + 2);
      CP_COMMIT();
    }

    const uint32_t stg = sb + buf * STAGE_BYTES;
#pragma unroll
    for (int k32 = 0; k32 < 2; k32++) {
      const uint32_t ko = (uint32_t)(k32 * 32) + lc4;
      // A fragments: m0 rows {wm*32+lr, +8}, m1 rows {+16, +24}
      uint32_t A0[4], A1[4];
      {
        const uint32_t a0 = stg + aRowOff + ko;
        A0[0] = lds32(a0);
        A0[1] = lds32(a0 + 8 * 80);
        A0[2] = lds32(a0 + 16);
        A0[3] = lds32(a0 + 8 * 80 + 16);
        const uint32_t a1 = a0 + 16 * 80;
        A1[0] = lds32(a1);
        A1[1] = lds32(a1 + 8 * 80);
        A1[2] = lds32(a1 + 16);
        A1[3] = lds32(a1 + 8 * 80 + 16);
      }
      // B fragments: n = wn*64 + f*8 + lr
      uint32_t Bf[8][2];
#pragma unroll
      for (int f = 0; f < 8; f++) {
        const uint32_t ba = stg + bRowOff + (uint32_t)(f * 8 * 80) + ko;
        Bf[f][0] = lds32(ba);
        Bf[f][1] = lds32(ba + 16);
      }
#pragma unroll
      for (int f = 0; f < 8; f++) mma16832(C[0][f], A0, Bf[f]);
#pragma unroll
      for (int f = 0; f < 8; f++) mma16832(C[1][f], A1, Bf[f]);
    }
    buf++; if (buf == NPIPE) buf = 0;
  }

  // epilogue: dequant -> bias -> relu -> *W2 -> per-row partials
  float lacc[4] = {0.0f, 0.0f, 0.0f, 0.0f};
  const int colbase = wn * 64 + (lane & 3) * 2;
#pragma unroll
  for (int ni = 0; ni < 8; ni++) {
    const int c0 = colbase + ni * 8;
    const float b10 = b1s[c0], b11 = b1s[c0 + 1];
    const float w20 = w2s[c0], w21 = w2s[c0 + 1];
#pragma unroll
    for (int mi = 0; mi < 2; mi++) {
      lacc[mi * 2 + 0] += fmaxf((float)C[mi][ni][0] * INVSC + b10, 0.0f) * w20
                        + fmaxf((float)C[mi][ni][1] * INVSC + b11, 0.0f) * w21;
      lacc[mi * 2 + 1] += fmaxf((float)C[mi][ni][2] * INVSC + b10, 0.0f) * w20
                        + fmaxf((float)C[mi][ni][3] * INVSC + b11, 0.0f) * w21;
    }
  }
#pragma unroll
  for (int j = 0; j < 4; j++) {
    lacc[j] += __shfl_xor_sync(0xFFFFFFFFu, lacc[j], 1);
    lacc[j] += __shfl_xor_sync(0xFFFFFFFFu, lacc[j], 2);
  }
  __syncthreads();
  if ((lane & 3) == 0) {
    const int r = lane >> 2;
    red[wn * 128 + wm * 32 + r]      = lacc[0];
    red[wn * 128 + wm * 32 + 8 + r]  = lacc[1];
    red[wn * 128 + wm * 32 + 16 + r] = lacc[2];
    red[wn * 128 + wm * 32 + 24 + r] = lacc[3];
  }
  __syncthreads();
  if (tid < BM)
    g_part[(size_t)(row0 + tid) * NHC + hc] =
        (red[tid] + red[128 + tid]) + (red[256 + tid] + red[384 + tid]);
}

// ---------------- top-k on approx + band extraction ----------------
__global__ __launch_bounds__(1024)
void topk_kernel(float* __restrict__ out_mask, uint32_t r2k0, uint32_t r2k1) {
  __shared__ float vals[SEQ];
  __shared__ float orig[SEQ];
  __shared__ unsigned char msk[SEQ];
  __shared__ float wv[32];
  __shared__ int wi[32];
  __shared__ float sAk;
  __shared__ int scnt, scsel;
  const int row = blockIdx.x;
  const int tid = threadIdx.x;
  const int w = tid >> 5, l = tid & 31;

#pragma unroll
  for (int j = 0; j < 4; j++) {
    int i = tid + j * 1024;
    uint32_t idx = (uint32_t)(row * SEQ + i);
    const float4* pp = (const float4*)&g_part[(size_t)idx * NHC];
    float4 a = pp[0], b = pp[1];
    float s = ((a.x + a.y) + (a.z + a.w)) + ((b.x + b.y) + (b.z + b.w));
    float v = s + gumbel_at(r2k0, r2k1, idx);
    vals[i] = v; orig[i] = v; msk[i] = 0;
  }
  if (tid == 0) { scnt = 0; scsel = 0; }
  __syncthreads();

  const int k = g_ksel;
  for (int it = 0; it < k; it++) {
    float best = -INFINITY; int bi = SEQ;
#pragma unroll
    for (int j = 0; j < 4; j++) {
      int i = tid + j * 1024;
      float v = vals[i];
      if (v > best || (v == best && i < bi)) { best = v; bi = i; }
    }
#pragma unroll
    for (int off = 16; off > 0; off >>= 1) {
      float ov = __shfl_down_sync(0xFFFFFFFFu, best, off);
      int oi = __shfl_down_sync(0xFFFFFFFFu, bi, off);
      if (ov > best || (ov == best && oi < bi)) { best = ov; bi = oi; }
    }
    if (l == 0) { wv[w] = best; wi[w] = bi; }
    __syncthreads();
    if (tid < 32) {
      best = wv[tid]; bi = wi[tid];
#pragma unroll
      for (int off = 16; off > 0; off >>= 1) {
        float ov = __shfl_down_sync(0xFFFFFFFFu, best, off);
        int oi = __shfl_down_sync(0xFFFFFFFFu, bi, off);
        if (ov > best || (ov == best && oi < bi)) { best = ov; bi = oi; }
      }
      if (tid == 0) {
        vals[bi] = -INFINITY; msk[bi] = 1;
        if (it == k - 1) sAk = best;
      }
    }
    __syncthreads();
  }

#pragma unroll
  for (int j = 0; j < 4; j++) {
    int i = tid + j * 1024;
    float m = (float)msk[i];
    out_mask[row * SEQ + i] = m;
    g_mask[row * SEQ + i] = m;
    if (fabsf(orig[i] - sAk) <= BANDW) {
      int p = atomicAdd(&scnt, 1);
      if (p < MAXBAND) g_band_idx[row * MAXBAND + p] = i;
      if (msk[i]) atomicAdd(&scsel, 1);
    }
  }
  __syncthreads();
  if (tid == 0) {
    g_bandcnt[row] = scnt < MAXBAND ? scnt : MAXBAND;
    g_bandsel[row] = scsel;
  }
}

// ---------------- refine: exact fp32 logits for band tokens ----------------
__global__ __launch_bounds__(256)
void refine_kernel(const float* __restrict__ X, const float* __restrict__ W1,
                   const float* __restrict__ b1, const float* __restrict__ W2) {
  const int jc = blockIdx.x, row = blockIdx.y, c0 = blockIdx.z * 16;
  const int cnt = g_bandcnt[row];
  if (c0 >= cnt) return;
  const int tid = threadIdx.x;
  const int tc = tid & 15, tj = tid >> 4;

  __shared__ int stok[16];
  __shared__ float Xs[16][33];
  __shared__ float Ws[32][132];
  __shared__ float part[16][17];

  if (tid < 16)
    stok[tid] = (c0 + tid < cnt) ? row * SEQ + g_band_idx[row * MAXBAND + c0 + tid]
                                 : row * SEQ;
  __syncthreads();

  float acc[8];
#pragma unroll
  for (int u = 0; u < 8; u++) acc[u] = 0.0f;

  for (int k0 = 0; k0 < DDIM; k0 += 32) {
#pragma unroll
    for (int p = 0; p < 2; p++) {
      int e = tid + p * 256;
      int c = e >> 5, kk = e & 31;
      Xs[c][kk] = X[(size_t)stok[c] * DDIM + k0 + kk];
    }
#pragma unroll
    for (int q = 0; q < 16; q++) {
      int f = tid + q * 256;
      int kk = f >> 7, jj = f & 127;
      Ws[kk][jj] = W1[(size_t)(k0 + kk) * HDIM + jc * 128 + jj];
    }
    __syncthreads();
#pragma unroll
    for (int kk = 0; kk < 32; kk++) {
      float x = Xs[tc][kk];
      const float4* wrow = (const float4*)&Ws[kk][tj * 8];
      float4 w0 = wrow[0], w1 = wrow[1];
      acc[0] = fmaf(x, w0.x, acc[0]); acc[1] = fmaf(x, w0.y, acc[1]);
      acc[2] = fmaf(x, w0.z, acc[2]); acc[3] = fmaf(x, w0.w, acc[3]);
      acc[4] = fmaf(x, w1.x, acc[4]); acc[5] = fmaf(x, w1.y, acc[5]);
      acc[6] = fmaf(x, w1.z, acc[6]); acc[7] = fmaf(x, w1.w, acc[7]);
    }
    __syncthreads();
  }

  float contrib = 0.0f;
#pragma unroll
  for (int u = 0; u < 8; u++) {
    int j = jc * 128 + tj * 8 + u;
    float h = acc[u] + b1[j];
    contrib += fmaxf(h, 0.0f) * W2[j];
  }
  part[tj][tc] = contrib;
  __syncthreads();
  if (tid < 16) {
    float s = 0.0f;
#pragma unroll
    for (int t = 0; t < 16; t++) s += part[t][tid];
    if (c0 + tid < cnt)
      g_band_partial[(row * MAXBAND + c0 + tid) * 16 + jc] = s;
  }
}

// ---------------- fixup: re-rank band by exact values ----------------
__global__ __launch_bounds__(MAXBAND)
void fixup_kernel(float* __restrict__ out_mask, uint32_t r2k0, uint32_t r2k1) {
  const int row = blockIdx.x, t = threadIdx.x;
  const int cnt = g_bandcnt[row], csel = g_bandsel[row];
  __shared__ float sv[MAXBAND], svv[MAXBAND];
  __shared__ int si[MAXBAND];

  float v = -INFINITY; int idx = -1;
  if (t < cnt) {
    idx = g_band_idx[row * MAXBAND + t];
    float s = 0.0f;
#pragma unroll
    for (int c = 0; c < 16; c++) s += g_band_partial[(row * MAXBAND + t) * 16 + c];
    v = s + gumbel_at(r2k0, r2k1, (uint32_t)(row * SEQ + idx));
  }
  svv[t] = v;
  __syncthreads();

  int chosen = 0;
  for (int it = 0; it < csel; it++) {
    sv[t] = svv[t]; si[t] = t;
    __syncthreads();
    for (int off = MAXBAND / 2; off > 0; off >>= 1) {
      if (t < off) {
        if (sv[t + off] > sv[t] || (sv[t + off] == sv[t] && si[t + off] < si[t])) {
          sv[t] = sv[t + off]; si[t] = si[t + off];
        }
      }
      __syncthreads();
    }
    if (t == si[0]) { chosen = 1; svv[t] = -INFINITY; }
    __syncthreads();
  }

  if (t < cnt) {
    float m = (float)chosen;
    out_mask[row * SEQ + idx] = m;
    g_mask[row * SEQ + idx] = m;
  }
}

// ---------------- scatter ----------------
__global__ __launch_bounds__(256)
void scatter_kernel(const float* __restrict__ X, float* __restrict__ out) {
  const int t = blockIdx.x;
  const int tid = threadIdx.x;
  const float m = g_mask[t];
  float4* dst = (float4*)(out + (size_t)t * DDIM);
  if (m != 0.0f) {
    const float4* src = (const float4*)(X + (size_t)t * DDIM);
    dst[tid] = src[tid];
  } else {
    dst[tid] = make_float4(0.0f, 0.0f, 0.0f, 0.0f);
  }
}

// ---------------- launch ----------------
extern "C" void kernel_launch(void* const* d_in, const int* in_sizes, int n_in,
                              void* d_out, int out_size) {
  const float* X  = (const float*)d_in[0];
  const float* W1 = (const float*)d_in[1];
  const float* b1 = (const float*)d_in[2];
  const float* W2 = (const float*)d_in[3];
  const float* kl = (const float*)d_in[5];

  float* out = (float*)d_out;
  float* out_mask = out + (size_t)NTOK * DDIM;
  float* out_ek   = out_mask + NTOK;

  uint32_t r1k0, r1k1, r2k0, r2k1;
  tf2x32(0u, 42u, 0u, 0u, &r1k0, &r1k1);
  tf2x32(0u, 42u, 0u, 1u, &r2k0, &r2k1);

  cudaFuncSetAttribute(gemm_logits_kernel,
                       cudaFuncAttributeMaxDynamicSharedMemorySize, DYN_SMEM);

  convX_kernel<<<(NTOK * DDIM / 4) / 256, 256>>>(X);
  convW_kernel<<<dim3(HDIM / 32, DDIM / 32), 256>>>(W1);
  k_select_kernel<<<1, 64>>>(kl, out_ek, r1k0, r1k1);
  gemm_logits_kernel<<<(NTOK / BM) * NHC, 512, DYN_SMEM>>>(b1, W2);
  topk_kernel<<<BATCH, 1024>>>(out_mask, r2k0, r2k1);
  refine_kernel<<<dim3(16, BATCH, MAXBAND / 16), 256>>>(X, W1, b1, W2);
  fixup_kernel<<<BATCH, MAXBAND>>>(out_mask, r2k0, r2k1);
  scatter_kernel<<<NTOK, 256>>>(X, out);
}

// round 12
// speedup vs baseline: 1.2758x; 1.2758x over previous
#include <cuda_runtime.h>
#include <cuda_bf16.h>
#include <stdint.h>
#include <math.h>

#define NTOK 32768
#define BATCH 8
#define SEQ 4096
#define DDIM 1024
#define HDIM 2048
#define MAXK 64

#define BM 128
#define BN 256
#define BK 64
#define NHC 8
#define UNIT_KSTAGES (DDIM / BK)    // 16

// smem: 3 stages of [A 128x144B = 18432][B 256x144B = 36864] = 55296 each
#define STAGE_BYTES 55296
#define NPIPE 3
#define B1S_OFF  (NPIPE * STAGE_BYTES)      // 165888
#define W2S_OFF  (B1S_OFF + 1024)
#define RED_OFF  (W2S_OFF + 1024)
#define DYN_SMEM (RED_OFF + 2048)           // 169984

#define MARGIN 0.03f
#define BANDW  0.06f
#define MAXBAND 64

// ---------------- scratch ----------------
static __device__ float g_part[(size_t)NTOK * NHC];
static __device__ float g_mask[NTOK];
static __device__ int   g_ksel;
static __device__ __nv_bfloat16 g_Xhi[(size_t)NTOK * DDIM];
static __device__ __nv_bfloat16 g_Whi[(size_t)HDIM * DDIM];  // n-major (transposed)
static __device__ int   g_band_idx[BATCH * MAXBAND];
static __device__ float g_band_partial[BATCH * MAXBAND * 16];
static __device__ int   g_bandcnt[BATCH];
static __device__ int   g_bandsel[BATCH];

// ---------------- PTX helpers ----------------
__device__ __forceinline__ uint32_t smem_u32(const void* p) {
  uint32_t a;
  asm("{ .reg .u64 t; cvta.to.shared.u64 t, %1; cvt.u32.u64 %0, t; }" : "=r"(a) : "l"(p));
  return a;
}
__device__ __forceinline__ void cp16(uint32_t saddr, const void* gaddr) {
  asm volatile("cp.async.cg.shared.global [%0], [%1], 16;" :: "r"(saddr), "l"(gaddr));
}
#define CP_COMMIT() asm volatile("cp.async.commit_group;" ::: "memory")
#define CP_WAIT1()  asm volatile("cp.async.wait_group 1;" ::: "memory")
#define CP_WAIT0()  asm volatile("cp.async.wait_group 0;" ::: "memory")

__device__ __forceinline__ void ldsm4(uint32_t* r, uint32_t addr) {
  asm volatile("ldmatrix.sync.aligned.m8n8.x4.shared.b16 {%0,%1,%2,%3}, [%4];"
               : "=r"(r[0]), "=r"(r[1]), "=r"(r[2]), "=r"(r[3]) : "r"(addr));
}
__device__ __forceinline__ void ldsm_b2(uint32_t (*b)[2], uint32_t addr) {
  uint32_t r[4];
  ldsm4(r, addr);
  b[0][0] = r[0]; b[0][1] = r[2];
  b[1][0] = r[1]; b[1][1] = r[3];
}
__device__ __forceinline__ void mma16816(float* c, const uint32_t* a, const uint32_t* b) {
  asm volatile("mma.sync.aligned.m16n8k16.row.col.f32.bf16.bf16.f32 "
               "{%0,%1,%2,%3}, {%4,%5,%6,%7}, {%8,%9}, {%0,%1,%2,%3};"
               : "+f"(c[0]), "+f"(c[1]), "+f"(c[2]), "+f"(c[3])
               : "r"(a[0]), "r"(a[1]), "r"(a[2]), "r"(a[3]), "r"(b[0]), "r"(b[1]));
}

// ---------------- threefry2x32-20 (JAX) ----------------
__host__ __device__ __forceinline__ void tf2x32(uint32_t k0, uint32_t k1,
                                                uint32_t x0, uint32_t x1,
                                                uint32_t* o0, uint32_t* o1) {
  uint32_t ks2 = k0 ^ k1 ^ 0x1BD11BDAu;
#define ROTL(v, d) (((v) << (d)) | ((v) >> (32 - (d))))
#define RND(r) { x0 += x1; x1 = ROTL(x1, r); x1 ^= x0; }
  x0 += k0; x1 += k1;
  RND(13) RND(15) RND(26) RND(6)
  x0 += k1; x1 += ks2 + 1u;
  RND(17) RND(29) RND(16) RND(24)
  x0 += ks2; x1 += k0 + 2u;
  RND(13) RND(15) RND(26) RND(6)
  x0 += k0; x1 += k1 + 3u;
  RND(17) RND(29) RND(16) RND(24)
  x0 += k1; x1 += ks2 + 4u;
  RND(13) RND(15) RND(26) RND(6)
  x0 += ks2; x1 += k0 + 5u;
#undef RND
#undef ROTL
  *o0 = x0; *o1 = x1;
}
__device__ __forceinline__ float gumbel_at(uint32_t k0, uint32_t k1, uint32_t idx) {
  uint32_t a, b;
  tf2x32(k0, k1, 0u, idx, &a, &b);
  uint32_t bits = a ^ b;
  float u = __uint_as_float((bits >> 9) | 0x3f800000u) - 1.0f;
  u = u + 1e-8f;
  u = fmaxf(1e-8f, u);
  return -logf(-logf(u));
}

// ---------------- conversion kernels (hi only) ----------------
__global__ __launch_bounds__(256) void convX_kernel(const float* __restrict__ X) {
  size_t i = (size_t)blockIdx.x * 256 + threadIdx.x;   // float4 index
  float4 v = ((const float4*)X)[i];
  __nv_bfloat162* H = (__nv_bfloat162*)g_Xhi;
  H[i * 2]     = __nv_bfloat162(__float2bfloat16(v.x), __float2bfloat16(v.y));
  H[i * 2 + 1] = __nv_bfloat162(__float2bfloat16(v.z), __float2bfloat16(v.w));
}

__global__ __launch_bounds__(256) void convW_kernel(const float* __restrict__ W1) {
  __shared__ float s[32][33];
  int n0 = blockIdx.x * 32;
  int k0 = blockIdx.y * 32;
  int tx = threadIdx.x & 31, ty = threadIdx.x >> 5;   // ty 0..7
#pragma unroll
  for (int j = 0; j < 4; j++) {
    int k = k0 + ty + j * 8;
    s[ty + j * 8][tx] = W1[(size_t)k * HDIM + n0 + tx];
  }
  __syncthreads();
#pragma unroll
  for (int j = 0; j < 4; j++) {
    int n = n0 + ty + j * 8;
    g_Whi[(size_t)n * DDIM + k0 + tx] = __float2bfloat16(s[tx][ty + j * 8]);
  }
}

// ---------------- k-select ----------------
__global__ void k_select_kernel(const float* __restrict__ k_logits,
                                float* __restrict__ out_ek,
                                uint32_t r1k0, uint32_t r1k1) {
  __shared__ float z[MAXK];
  int t = threadIdx.x;
  if (t < MAXK) z[t] = k_logits[t] + gumbel_at(r1k0, r1k1, (uint32_t)t);
  __syncthreads();
  if (t == 0) {
    float m = -INFINITY; int am = 0;
    for (int i = 0; i < MAXK; i++) if (z[i] > m) { m = z[i]; am = i; }
    float s = 0.0f, e[MAXK];
    for (int i = 0; i < MAXK; i++) { e[i] = expf(z[i] - m); s += e[i]; }
    float ek = 0.0f;
    for (int i = 0; i < MAXK; i++) ek += (e[i] / s) * (float)(i + 1);
    out_ek[0] = ek;
    g_ksel = am + 1;
  }
}

// ---------------- 1-pass bf16 HMMA GEMM -> per-chunk partial logits ----------------
// grid = 2048 units (256 row-blocks x 8 h-chunks), 256 threads / 8 warps.
// Warp tile 64x64 (C = 128 fp32 regs): 8 ldsm.x4 per 32 MMAs -> 128 B/MMA.
__global__ __launch_bounds__(256, 1)
void gemm_logits_kernel(const float* __restrict__ b1, const float* __restrict__ W2) {
  extern __shared__ char smem[];
  const uint32_t sb = smem_u32(smem);
  const int tid = threadIdx.x;
  const int lane = tid & 31;
  const int wid = tid >> 5;
  const int wm = wid & 1;           // 0..1 (m, 64-row slices)
  const int wn = wid >> 1;          // 0..3 (n, 64-col slices)
  const int row0 = (blockIdx.x >> 3) * BM;
  const int hc = blockIdx.x & 7;

  float* b1s = (float*)(smem + B1S_OFF);
  float* w2s = (float*)(smem + W2S_OFF);
  float* red = (float*)(smem + RED_OFF);

  // loader: A 1024 + B 2048 16B-chunks = 12 per thread
  const int arow = tid >> 3, ach = tid & 7;   // base row 0..31, 16B chunk 0..7
  const char* pXb = (const char*)g_Xhi + (((size_t)(row0 + arow)) << 11) + ach * 16;
  const char* pWb = (const char*)g_Whi + (((size_t)(hc * BN + arow)) << 11) + ach * 16;
  const uint32_t sA = (uint32_t)(arow * 144 + ach * 16);

#define ISSUE_STAGE(stgbase, ks) do {                                        \
    const uint32_t _stg = (stgbase);                                         \
    const size_t _ko = ((size_t)(ks)) << 7;                                  \
    _Pragma("unroll")                                                        \
    for (int j = 0; j < 4; j++)                                              \
      cp16(_stg + sA + j * 4608, pXb + (size_t)j * 65536 + _ko);             \
    _Pragma("unroll")                                                        \
    for (int j = 0; j < 8; j++)                                              \
      cp16(_stg + 18432 + sA + j * 4608, pWb + (size_t)j * 65536 + _ko);     \
  } while (0)

  ISSUE_STAGE(sb, 0);
  CP_COMMIT();
  ISSUE_STAGE(sb + STAGE_BYTES, 1);
  CP_COMMIT();

  // stage this chunk's b1/W2 (256 floats each); published by loop barrier
  b1s[tid] = b1[hc * BN + tid];
  w2s[tid] = W2[hc * BN + tid];

  float C[4][8][4];
#pragma unroll
  for (int mi = 0; mi < 4; mi++)
#pragma unroll
    for (int ni = 0; ni < 8; ni++)
#pragma unroll
      for (int j = 0; j < 4; j++) C[mi][ni][j] = 0.0f;

  const int lr = lane & 15, lh = lane >> 4;
  const uint32_t aOff = (uint32_t)((wm * 64 + lr) * 144 + lh * 16);
  const uint32_t bOff = (uint32_t)(18432 + (wn * 64 + lr) * 144 + lh * 16);

  int buf = 0;
  for (int s = 0; s < UNIT_KSTAGES; s++) {
    if (s + 2 < UNIT_KSTAGES) CP_WAIT1(); else CP_WAIT0();
    __syncthreads();   // publish buf s; certify compute(s-1) done
    if (s + 2 < UNIT_KSTAGES) {
      int b2i = buf + 2; if (b2i >= NPIPE) b2i -= NPIPE;
      ISSUE_STAGE(sb + b2i * STAGE_BYTES, s + 2);
      CP_COMMIT();
    }

    const uint32_t aB = sb + buf * STAGE_BYTES + aOff;
    const uint32_t bB = sb + buf * STAGE_BYTES + bOff;
#pragma unroll
    for (int k16 = 0; k16 < 4; k16++) {
      const uint32_t kofs = (uint32_t)(k16 * 32);
      uint32_t a[4][4], bb[8][2];
#pragma unroll
      for (int mi = 0; mi < 4; mi++)
        ldsm4(a[mi], aB + (uint32_t)(mi * 16 * 144) + kofs);
#pragma unroll
      for (int nt2 = 0; nt2 < 4; nt2++)
        ldsm_b2(bb + 2 * nt2, bB + (uint32_t)(nt2 * 16 * 144) + kofs);
#pragma unroll
      for (int mi = 0; mi < 4; mi++)
#pragma unroll
        for (int f = 0; f < 8; f++) mma16816(C[mi][f], a[mi], bb[f]);
    }
    buf++; if (buf == NPIPE) buf = 0;
  }

  // epilogue: bias -> relu -> *W2 -> per-row partial for this h-chunk
  float lacc[8];
#pragma unroll
  for (int j = 0; j < 8; j++) lacc[j] = 0.0f;
  const int colbase = wn * 64 + (lane & 3) * 2;
#pragma unroll
  for (int ni = 0; ni < 8; ni++) {
    const int c0 = colbase + ni * 8;
    const float b10 = b1s[c0], b11 = b1s[c0 + 1];
    const float w20 = w2s[c0], w21 = w2s[c0 + 1];
#pragma unroll
    for (int mi = 0; mi < 4; mi++) {
      lacc[mi * 2 + 0] += fmaxf(C[mi][ni][0] + b10, 0.0f) * w20
                        + fmaxf(C[mi][ni][1] + b11, 0.0f) * w21;
      lacc[mi * 2 + 1] += fmaxf(C[mi][ni][2] + b10, 0.0f) * w20
                        + fmaxf(C[mi][ni][3] + b11, 0.0f) * w21;
    }
  }
#pragma unroll
  for (int j = 0; j < 8; j++) {
    lacc[j] += __shfl_xor_sync(0xFFFFFFFFu, lacc[j], 1);
    lacc[j] += __shfl_xor_sync(0xFFFFFFFFu, lacc[j], 2);
  }
  __syncthreads();
  if ((lane & 3) == 0) {
    const int r = lane >> 2;
#pragma unroll
    for (int mi = 0; mi < 4; mi++) {
      red[wn * 128 + wm * 64 + mi * 16 + r]     = lacc[mi * 2 + 0];
      red[wn * 128 + wm * 64 + mi * 16 + 8 + r] = lacc[mi * 2 + 1];
    }
  }
  __syncthreads();
  if (tid < BM)
    g_part[(size_t)(row0 + tid) * NHC + hc] =
        (red[tid] + red[128 + tid]) + (red[256 + tid] + red[384 + tid]);
}

// ---------------- top-k on approx + band extraction ----------------
__global__ __launch_bounds__(1024)
void topk_kernel(float* __restrict__ out_mask, uint32_t r2k0, uint32_t r2k1) {
  __shared__ float vals[SEQ];
  __shared__ float orig[SEQ];
  __shared__ unsigned char msk[SEQ];
  __shared__ float wv[32];
  __shared__ int wi[32];
  __shared__ float sAk;
  __shared__ int scnt, scsel;
  const int row = blockIdx.x;
  const int tid = threadIdx.x;
  const int w = tid >> 5, l = tid & 31;

#pragma unroll
  for (int j = 0; j < 4; j++) {
    int i = tid + j * 1024;
    uint32_t idx = (uint32_t)(row * SEQ + i);
    const float4* pp = (const float4*)&g_part[(size_t)idx * NHC];
    float4 a = pp[0], b = pp[1];
    float s = ((a.x + a.y) + (a.z + a.w)) + ((b.x + b.y) + (b.z + b.w));
    float v = s + gumbel_at(r2k0, r2k1, idx);
    vals[i] = v; orig[i] = v; msk[i] = 0;
  }
  if (tid == 0) { scnt = 0; scsel = 0; }
  __syncthreads();

  const int k = g_ksel;
  for (int it = 0; it < k; it++) {
    float best = -INFINITY; int bi = SEQ;
#pragma unroll
    for (int j = 0; j < 4; j++) {
      int i = tid + j * 1024;
      float v = vals[i];
      if (v > best || (v == best && i < bi)) { best = v; bi = i; }
    }
#pragma unroll
    for (int off = 16; off > 0; off >>= 1) {
      float ov = __shfl_down_sync(0xFFFFFFFFu, best, off);
      int oi = __shfl_down_sync(0xFFFFFFFFu, bi, off);
      if (ov > best || (ov == best && oi < bi)) { best = ov; bi = oi; }
    }
    if (l == 0) { wv[w] = best; wi[w] = bi; }
    __syncthreads();
    if (tid < 32) {
      best = wv[tid]; bi = wi[tid];
#pragma unroll
      for (int off = 16; off > 0; off >>= 1) {
        float ov = __shfl_down_sync(0xFFFFFFFFu, best, off);
        int oi = __shfl_down_sync(0xFFFFFFFFu, bi, off);
        if (ov > best || (ov == best && oi < bi)) { best = ov; bi = oi; }
      }
      if (tid == 0) {
        vals[bi] = -INFINITY; msk[bi] = 1;
        if (it == k - 1) sAk = best;
      }
    }
    __syncthreads();
  }

#pragma unroll
  for (int j = 0; j < 4; j++) {
    int i = tid + j * 1024;
    float m = (float)msk[i];
    out_mask[row * SEQ + i] = m;
    g_mask[row * SEQ + i] = m;
    if (fabsf(orig[i] - sAk) <= BANDW) {
      int p = atomicAdd(&scnt, 1);
      if (p < MAXBAND) g_band_idx[row * MAXBAND + p] = i;
      if (msk[i]) atomicAdd(&scsel, 1);
    }
  }
  __syncthreads();
  if (tid == 0) {
    g_bandcnt[row] = scnt < MAXBAND ? scnt : MAXBAND;
    g_bandsel[row] = scsel;
  }
}

// ---------------- refine: exact fp32 logits for band tokens ----------------
__global__ __launch_bounds__(256)
void refine_kernel(const float* __restrict__ X, const float* __restrict__ W1,
                   const float* __restrict__ b1, const float* __restrict__ W2) {
  const int jc = blockIdx.x, row = blockIdx.y, c0 = blockIdx.z * 16;
  const int cnt = g_bandcnt[row];
  if (c0 >= cnt) return;
  const int tid = threadIdx.x;
  const int tc = tid & 15, tj = tid >> 4;

  __shared__ int stok[16];
  __shared__ float Xs[16][33];
  __shared__ float Ws[32][132];
  __shared__ float part[16][17];

  if (tid < 16)
    stok[tid] = (c0 + tid < cnt) ? row * SEQ + g_band_idx[row * MAXBAND + c0 + tid]
                                 : row * SEQ;
  __syncthreads();

  float acc[8];
#pragma unroll
  for (int u = 0; u < 8; u++) acc[u] = 0.0f;

  for (int k0 = 0; k0 < DDIM; k0 += 32) {
#pragma unroll
    for (int p = 0; p < 2; p++) {
      int e = tid + p * 256;
      int c = e >> 5, kk = e & 31;
      Xs[c][kk] = X[(size_t)stok[c] * DDIM + k0 + kk];
    }
#pragma unroll
    for (int q = 0; q < 16; q++) {
      int f = tid + q * 256;
      int kk = f >> 7, jj = f & 127;
      Ws[kk][jj] = W1[(size_t)(k0 + kk) * HDIM + jc * 128 + jj];
    }
    __syncthreads();
#pragma unroll
    for (int kk = 0; kk < 32; kk++) {
      float x = Xs[tc][kk];
      const float4* wrow = (const float4*)&Ws[kk][tj * 8];
      float4 w0 = wrow[0], w1 = wrow[1];
      acc[0] = fmaf(x, w0.x, acc[0]); acc[1] = fmaf(x, w0.y, acc[1]);
      acc[2] = fmaf(x, w0.z, acc[2]); acc[3] = fmaf(x, w0.w, acc[3]);
      acc[4] = fmaf(x, w1.x, acc[4]); acc[5] = fmaf(x, w1.y, acc[5]);
      acc[6] = fmaf(x, w1.z, acc[6]); acc[7] = fmaf(x, w1.w, acc[7]);
    }
    __syncthreads();
  }

  float contrib = 0.0f;
#pragma unroll
  for (int u = 0; u < 8; u++) {
    int j = jc * 128 + tj * 8 + u;
    float h = acc[u] + b1[j];
    contrib += fmaxf(h, 0.0f) * W2[j];
  }
  part[tj][tc] = contrib;
  __syncthreads();
  if (tid < 16) {
    float s = 0.0f;
#pragma unroll
    for (int t = 0; t < 16; t++) s += part[t][tid];
    if (c0 + tid < cnt)
      g_band_partial[(row * MAXBAND + c0 + tid) * 16 + jc] = s;
  }
}

// ---------------- fixup: re-rank band by exact values ----------------
__global__ __launch_bounds__(64)
void fixup_kernel(float* __restrict__ out_mask, uint32_t r2k0, uint32_t r2k1) {
  const int row = blockIdx.x, t = threadIdx.x;
  const int cnt = g_bandcnt[row], csel = g_bandsel[row];
  __shared__ float sv[64], svv[64];
  __shared__ int si[64];

  float v = -INFINITY; int idx = -1;
  if (t < cnt) {
    idx = g_band_idx[row * MAXBAND + t];
    float s = 0.0f;
#pragma unroll
    for (int c = 0; c < 16; c++) s += g_band_partial[(row * MAXBAND + t) * 16 + c];
    v = s + gumbel_at(r2k0, r2k1, (uint32_t)(row * SEQ + idx));
  }
  svv[t] = v;
  __syncthreads();

  int chosen = 0;
  for (int it = 0; it < csel; it++) {
    sv[t] = svv[t]; si[t] = t;
    __syncthreads();
    for (int off = 32; off > 0; off >>= 1) {
      if (t < off) {
        if (sv[t + off] > sv[t] || (sv[t + off] == sv[t] && si[t + off] < si[t])) {
          sv[t] = sv[t + off]; si[t] = si[t + off];
        }
      }
      __syncthreads();
    }
    if (t == si[0]) { chosen = 1; svv[t] = -INFINITY; }
    __syncthreads();
  }

  if (t < cnt) {
    float m = (float)chosen;
    out_mask[row * SEQ + idx] = m;
    g_mask[row * SEQ + idx] = m;
  }
}

// ---------------- scatter ----------------
__global__ __launch_bounds__(256)
void scatter_kernel(const float* __restrict__ X, float* __restrict__ out) {
  const int t = blockIdx.x;
  const int tid = threadIdx.x;
  const float m = g_mask[t];
  float4* dst = (float4*)(out + (size_t)t * DDIM);
  if (m != 0.0f) {
    const float4* src = (const float4*)(X + (size_t)t * DDIM);
    dst[tid] = src[tid];
  } else {
    dst[tid] = make_float4(0.0f, 0.0f, 0.0f, 0.0f);
  }
}

// ---------------- launch ----------------
extern "C" void kernel_launch(void* const* d_in, const int* in_sizes, int n_in,
                              void* d_out, int out_size) {
  const float* X  = (const float*)d_in[0];
  const float* W1 = (const float*)d_in[1];
  const float* b1 = (const float*)d_in[2];
  const float* W2 = (const float*)d_in[3];
  const float* kl = (const float*)d_in[5];

  float* out = (float*)d_out;
  float* out_mask = out + (size_t)NTOK * DDIM;
  float* out_ek   = out_mask + NTOK;

  uint32_t r1k0, r1k1, r2k0, r2k1;
  tf2x32(0u, 42u, 0u, 0u, &r1k0, &r1k1);
  tf2x32(0u, 42u, 0u, 1u, &r2k0, &r2k1);

  cudaFuncSetAttribute(gemm_logits_kernel,
                       cudaFuncAttributeMaxDynamicSharedMemorySize, DYN_SMEM);

  convX_kernel<<<(NTOK * DDIM / 4) / 256, 256>>>(X);
  convW_kernel<<<dim3(HDIM / 32, DDIM / 32), 256>>>(W1);
  k_select_kernel<<<1, 64>>>(kl, out_ek, r1k0, r1k1);
  gemm_logits_kernel<<<(NTOK / BM) * NHC, 256, DYN_SMEM>>>(b1, W2);
  topk_kernel<<<BATCH, 1024>>>(out_mask, r2k0, r2k1);
  refine_kernel<<<dim3(16, BATCH, 4), 256>>>(X, W1, b1, W2);
  fixup_kernel<<<BATCH, 64>>>(out_mask, r2k0, r2k1);
  scatter_kernel<<<NTOK, 256>>>(X, out);
}

// round 13
// speedup vs baseline: 1.9289x; 1.5119x over previous
#include <cuda_runtime.h>
#include <cuda_bf16.h>
#include <stdint.h>
#include <math.h>

#define NTOK 32768
#define BATCH 8
#define SEQ 4096
#define DDIM 1024
#define HDIM 2048
#define MAXK 64

#define BM 128
#define BN 256
#define BK 64
#define NHC 8
#define UNIT_KSTAGES (DDIM / BK)    // 16

// smem: 3 stages of [A 128x144B = 18432][B 256x144B = 36864] = 55296 each
#define STAGE_BYTES 55296
#define NPIPE 3
#define B1S_OFF  (NPIPE * STAGE_BYTES)      // 165888
#define W2S_OFF  (B1S_OFF + 1024)
#define RED_OFF  (W2S_OFF + 1024)
#define DYN_SMEM (RED_OFF + 2048)           // 169984

#define MARGIN 0.03f
#define BANDW  0.06f
#define MAXBAND 64

// ---------------- scratch ----------------
static __device__ float g_part[(size_t)NTOK * NHC];
static __device__ float g_mask[NTOK];
static __device__ int   g_ksel;
static __device__ __nv_bfloat16 g_Xhi[(size_t)NTOK * DDIM];
static __device__ __nv_bfloat16 g_Whi[(size_t)HDIM * DDIM];  // n-major (transposed)
static __device__ int   g_band_idx[BATCH * MAXBAND];
static __device__ float g_band_partial[BATCH * MAXBAND * 16];
static __device__ int   g_bandcnt[BATCH];
static __device__ int   g_bandsel[BATCH];

// ---------------- PTX helpers ----------------
__device__ __forceinline__ uint32_t smem_u32(const void* p) {
  uint32_t a;
  asm("{ .reg .u64 t; cvta.to.shared.u64 t, %1; cvt.u32.u64 %0, t; }" : "=r"(a) : "l"(p));
  return a;
}
__device__ __forceinline__ void cp16(uint32_t saddr, const void* gaddr) {
  asm volatile("cp.async.cg.shared.global [%0], [%1], 16;" :: "r"(saddr), "l"(gaddr));
}
#define CP_COMMIT() asm volatile("cp.async.commit_group;" ::: "memory")
#define CP_WAIT1()  asm volatile("cp.async.wait_group 1;" ::: "memory")
#define CP_WAIT0()  asm volatile("cp.async.wait_group 0;" ::: "memory")

__device__ __forceinline__ void ldsm4(uint32_t* r, uint32_t addr) {
  asm volatile("ldmatrix.sync.aligned.m8n8.x4.shared.b16 {%0,%1,%2,%3}, [%4];"
               : "=r"(r[0]), "=r"(r[1]), "=r"(r[2]), "=r"(r[3]) : "r"(addr));
}
__device__ __forceinline__ void ldsm_b2(uint32_t (*b)[2], uint32_t addr) {
  uint32_t r[4];
  ldsm4(r, addr);
  b[0][0] = r[0]; b[0][1] = r[2];
  b[1][0] = r[1]; b[1][1] = r[3];
}
__device__ __forceinline__ void mma16816(float* c, const uint32_t* a, const uint32_t* b) {
  asm volatile("mma.sync.aligned.m16n8k16.row.col.f32.bf16.bf16.f32 "
               "{%0,%1,%2,%3}, {%4,%5,%6,%7}, {%8,%9}, {%0,%1,%2,%3};"
               : "+f"(c[0]), "+f"(c[1]), "+f"(c[2]), "+f"(c[3])
               : "r"(a[0]), "r"(a[1]), "r"(a[2]), "r"(a[3]), "r"(b[0]), "r"(b[1]));
}

// ---------------- threefry2x32-20 (JAX) ----------------
__host__ __device__ __forceinline__ void tf2x32(uint32_t k0, uint32_t k1,
                                                uint32_t x0, uint32_t x1,
                                                uint32_t* o0, uint32_t* o1) {
  uint32_t ks2 = k0 ^ k1 ^ 0x1BD11BDAu;
#define ROTL(v, d) (((v) << (d)) | ((v) >> (32 - (d))))
#define RND(r) { x0 += x1; x1 = ROTL(x1, r); x1 ^= x0; }
  x0 += k0; x1 += k1;
  RND(13) RND(15) RND(26) RND(6)
  x0 += k1; x1 += ks2 + 1u;
  RND(17) RND(29) RND(16) RND(24)
  x0 += ks2; x1 += k0 + 2u;
  RND(13) RND(15) RND(26) RND(6)
  x0 += k0; x1 += k1 + 3u;
  RND(17) RND(29) RND(16) RND(24)
  x0 += k1; x1 += ks2 + 4u;
  RND(13) RND(15) RND(26) RND(6)
  x0 += ks2; x1 += k0 + 5u;
#undef RND
#undef ROTL
  *o0 = x0; *o1 = x1;
}
__device__ __forceinline__ float gumbel_at(uint32_t k0, uint32_t k1, uint32_t idx) {
  uint32_t a, b;
  tf2x32(k0, k1, 0u, idx, &a, &b);
  uint32_t bits = a ^ b;
  float u = __uint_as_float((bits >> 9) | 0x3f800000u) - 1.0f;
  u = u + 1e-8f;
  u = fmaxf(1e-8f, u);
  return -logf(-logf(u));
}

// ---------------- conversion kernels (hi only) ----------------
__global__ __launch_bounds__(256) void convX_kernel(const float* __restrict__ X) {
  size_t i = (size_t)blockIdx.x * 256 + threadIdx.x;   // float4 index
  float4 v = ((const float4*)X)[i];
  __nv_bfloat162* H = (__nv_bfloat162*)g_Xhi;
  H[i * 2]     = __nv_bfloat162(__float2bfloat16(v.x), __float2bfloat16(v.y));
  H[i * 2 + 1] = __nv_bfloat162(__float2bfloat16(v.z), __float2bfloat16(v.w));
}

__global__ __launch_bounds__(256) void convW_kernel(const float* __restrict__ W1) {
  __shared__ float s[32][33];
  int n0 = blockIdx.x * 32;
  int k0 = blockIdx.y * 32;
  int tx = threadIdx.x & 31, ty = threadIdx.x >> 5;   // ty 0..7
#pragma unroll
  for (int j = 0; j < 4; j++) {
    int k = k0 + ty + j * 8;
    s[ty + j * 8][tx] = W1[(size_t)k * HDIM + n0 + tx];
  }
  __syncthreads();
#pragma unroll
  for (int j = 0; j < 4; j++) {
    int n = n0 + ty + j * 8;
    g_Whi[(size_t)n * DDIM + k0 + tx] = __float2bfloat16(s[tx][ty + j * 8]);
  }
}

// ---------------- k-select ----------------
__global__ void k_select_kernel(const float* __restrict__ k_logits,
                                float* __restrict__ out_ek,
                                uint32_t r1k0, uint32_t r1k1) {
  __shared__ float z[MAXK];
  int t = threadIdx.x;
  if (t < MAXK) z[t] = k_logits[t] + gumbel_at(r1k0, r1k1, (uint32_t)t);
  __syncthreads();
  if (t == 0) {
    float m = -INFINITY; int am = 0;
    for (int i = 0; i < MAXK; i++) if (z[i] > m) { m = z[i]; am = i; }
    float s = 0.0f, e[MAXK];
    for (int i = 0; i < MAXK; i++) { e[i] = expf(z[i] - m); s += e[i]; }
    float ek = 0.0f;
    for (int i = 0; i < MAXK; i++) ek += (e[i] / s) * (float)(i + 1);
    out_ek[0] = ek;
    g_ksel = am + 1;
  }
}

// ---------------- 1-pass bf16 HMMA GEMM -> per-chunk partial logits ----------------
// grid = 2048 units (256 row-blocks x 8 h-chunks), 512 threads, warp tile 32x64.
// Per-warp k16 order staggered by (wid & 3) to de-phase LDSM vs MMA across warps.
__global__ __launch_bounds__(512, 1)
void gemm_logits_kernel(const float* __restrict__ b1, const float* __restrict__ W2) {
  extern __shared__ char smem[];
  const uint32_t sb = smem_u32(smem);
  const int tid = threadIdx.x;
  const int lane = tid & 31;
  const int wid = tid >> 5;
  const int wm = wid & 3;           // 0..3 (m, 32-row slices)
  const int wn = wid >> 2;          // 0..3 (n, 64-col slices)
  const int row0 = (blockIdx.x >> 3) * BM;
  const int hc = blockIdx.x & 7;

  float* b1s = (float*)(smem + B1S_OFF);
  float* w2s = (float*)(smem + W2S_OFF);
  float* red = (float*)(smem + RED_OFF);

  // loader: A 1024 chunks (2/thread), B 2048 chunks (4/thread); 16B chunks
  const int cr = tid >> 3, ch = tid & 7;   // row 0..63 base, 16B-half 0..7
  const char* pXb = (const char*)g_Xhi + (((size_t)(row0 + cr)) << 11) + ch * 16;
  const char* pWb = (const char*)g_Whi + (((size_t)(hc * BN + cr)) << 11) + ch * 16;
  const uint32_t sA = (uint32_t)(cr * 144 + ch * 16);

#define ISSUE_STAGE(stgbase, ks) do {                                        \
    const uint32_t _stg = (stgbase);                                         \
    const size_t _ko = ((size_t)(ks)) << 7;                                  \
    cp16(_stg + sA,                  pXb + _ko);                             \
    cp16(_stg + sA + 9216,           pXb + (64ull << 11) + _ko);             \
    cp16(_stg + 18432 + sA,          pWb + _ko);                             \
    cp16(_stg + 18432 + sA + 9216,   pWb + (64ull << 11) + _ko);             \
    cp16(_stg + 18432 + sA + 18432,  pWb + (128ull << 11) + _ko);            \
    cp16(_stg + 18432 + sA + 27648,  pWb + (192ull << 11) + _ko);            \
  } while (0)

  // prefetch 2 stages
  ISSUE_STAGE(sb, 0);
  CP_COMMIT();
  ISSUE_STAGE(sb + STAGE_BYTES, 1);
  CP_COMMIT();

  // stage this chunk's b1/W2 (256 floats each); published by loop barrier
  if (tid < 256) {
    b1s[tid] = b1[hc * BN + tid];
    w2s[tid] = W2[hc * BN + tid];
  }

  float C[2][8][4];
#pragma unroll
  for (int mi = 0; mi < 2; mi++)
#pragma unroll
    for (int ni = 0; ni < 8; ni++)
#pragma unroll
      for (int j = 0; j < 4; j++) C[mi][ni][j] = 0.0f;

  const int lr = lane & 15, lh = lane >> 4;
  const uint32_t aOff = (uint32_t)((wm * 32 + lr) * 144 + lh * 16);
  const uint32_t bOff = (uint32_t)(18432 + (wn * 64 + lr) * 144 + lh * 16);

  int buf = 0;
  for (int s = 0; s < UNIT_KSTAGES; s++) {
    if (s + 2 < UNIT_KSTAGES) CP_WAIT1(); else CP_WAIT0();
    __syncthreads();   // publish buf s; certify compute(s-1) done
    if (s + 2 < UNIT_KSTAGES) {
      int b2i = buf + 2; if (b2i >= NPIPE) b2i -= NPIPE;
      ISSUE_STAGE(sb + b2i * STAGE_BYTES, s + 2);
      CP_COMMIT();
    }

    const uint32_t aB = sb + buf * STAGE_BYTES + aOff;
    const uint32_t bB = sb + buf * STAGE_BYTES + bOff;
#pragma unroll
    for (int jj = 0; jj < 4; jj++) {
      // warp-staggered k16 order: warps in different phases de-serialize
      // the smem crossbar (LDSM) vs tensor (MMA) pipes. Per-warp FP order is
      // fixed -> deterministic; band-refine makes selection exact anyway.
      const int k16 = (jj + wm) & 3;
      const uint32_t kofs = (uint32_t)(k16 * 32);
      uint32_t ah[2][4], bb0[4][2], bb1[4][2];
      ldsm4(ah[0], aB + kofs);
      ldsm4(ah[1], aB + 16 * 144 + kofs);
      ldsm_b2(bb0 + 0, bB + kofs);
      ldsm_b2(bb0 + 2, bB + 16 * 144 + kofs);
      ldsm_b2(bb1 + 0, bB + 2 * (16 * 144) + kofs);
      ldsm_b2(bb1 + 2, bB + 3 * (16 * 144) + kofs);
#pragma unroll
      for (int mi = 0; mi < 2; mi++)
#pragma unroll
        for (int ni = 0; ni < 4; ni++) mma16816(C[mi][ni], ah[mi], bb0[ni]);
#pragma unroll
      for (int mi = 0; mi < 2; mi++)
#pragma unroll
        for (int ni = 0; ni < 4; ni++) mma16816(C[mi][ni + 4], ah[mi], bb1[ni]);
    }
    buf++; if (buf == NPIPE) buf = 0;
  }

  // epilogue: bias -> relu -> *W2 -> per-row partial for this h-chunk
  float lacc[4] = {0.0f, 0.0f, 0.0f, 0.0f};
  const int colbase = wn * 64 + (lane & 3) * 2;
#pragma unroll
  for (int ni = 0; ni < 8; ni++) {
    const int c0 = colbase + ni * 8;
    const float b10 = b1s[c0], b11 = b1s[c0 + 1];
    const float w20 = w2s[c0], w21 = w2s[c0 + 1];
#pragma unroll
    for (int mi = 0; mi < 2; mi++) {
      lacc[mi * 2 + 0] += fmaxf(C[mi][ni][0] + b10, 0.0f) * w20
                        + fmaxf(C[mi][ni][1] + b11, 0.0f) * w21;
      lacc[mi * 2 + 1] += fmaxf(C[mi][ni][2] + b10, 0.0f) * w20
                        + fmaxf(C[mi][ni][3] + b11, 0.0f) * w21;
    }
  }
#pragma unroll
  for (int j = 0; j < 4; j++) {
    lacc[j] += __shfl_xor_sync(0xFFFFFFFFu, lacc[j], 1);
    lacc[j] += __shfl_xor_sync(0xFFFFFFFFu, lacc[j], 2);
  }
  __syncthreads();
  if ((lane & 3) == 0) {
    const int r = lane >> 2;
    red[wn * 128 + wm * 32 + r]      = lacc[0];
    red[wn * 128 + wm * 32 + 8 + r]  = lacc[1];
    red[wn * 128 + wm * 32 + 16 + r] = lacc[2];
    red[wn * 128 + wm * 32 + 24 + r] = lacc[3];
  }
  __syncthreads();
  if (tid < BM)
    g_part[(size_t)(row0 + tid) * NHC + hc] =
        (red[tid] + red[128 + tid]) + (red[256 + tid] + red[384 + tid]);
}

// ---------------- top-k on approx + band extraction ----------------
__global__ __launch_bounds__(1024)
void topk_kernel(float* __restrict__ out_mask, uint32_t r2k0, uint32_t r2k1) {
  __shared__ float vals[SEQ];
  __shared__ float orig[SEQ];
  __shared__ unsigned char msk[SEQ];
  __shared__ float wv[32];
  __shared__ int wi[32];
  __shared__ float sAk;
  __shared__ int scnt, scsel;
  const int row = blockIdx.x;
  const int tid = threadIdx.x;
  const int w = tid >> 5, l = tid & 31;

#pragma unroll
  for (int j = 0; j < 4; j++) {
    int i = tid + j * 1024;
    uint32_t idx = (uint32_t)(row * SEQ + i);
    const float4* pp = (const float4*)&g_part[(size_t)idx * NHC];
    float4 a = pp[0], b = pp[1];
    float s = ((a.x + a.y) + (a.z + a.w)) + ((b.x + b.y) + (b.z + b.w));
    float v = s + gumbel_at(r2k0, r2k1, idx);
    vals[i] = v; orig[i] = v; msk[i] = 0;
  }
  if (tid == 0) { scnt = 0; scsel = 0; }
  __syncthreads();

  const int k = g_ksel;
  for (int it = 0; it < k; it++) {
    float best = -INFINITY; int bi = SEQ;
#pragma unroll
    for (int j = 0; j < 4; j++) {
      int i = tid + j * 1024;
      float v = vals[i];
      if (v > best || (v == best && i < bi)) { best = v; bi = i; }
    }
#pragma unroll
    for (int off = 16; off > 0; off >>= 1) {
      float ov = __shfl_down_sync(0xFFFFFFFFu, best, off);
      int oi = __shfl_down_sync(0xFFFFFFFFu, bi, off);
      if (ov > best || (ov == best && oi < bi)) { best = ov; bi = oi; }
    }
    if (l == 0) { wv[w] = best; wi[w] = bi; }
    __syncthreads();
    if (tid < 32) {
      best = wv[tid]; bi = wi[tid];
#pragma unroll
      for (int off = 16; off > 0; off >>= 1) {
        float ov = __shfl_down_sync(0xFFFFFFFFu, best, off);
        int oi = __shfl_down_sync(0xFFFFFFFFu, bi, off);
        if (ov > best || (ov == best && oi < bi)) { best = ov; bi = oi; }
      }
      if (tid == 0) {
        vals[bi] = -INFINITY; msk[bi] = 1;
        if (it == k - 1) sAk = best;
      }
    }
    __syncthreads();
  }

#pragma unroll
  for (int j = 0; j < 4; j++) {
    int i = tid + j * 1024;
    float m = (float)msk[i];
    out_mask[row * SEQ + i] = m;
    g_mask[row * SEQ + i] = m;
    if (fabsf(orig[i] - sAk) <= BANDW) {
      int p = atomicAdd(&scnt, 1);
      if (p < MAXBAND) g_band_idx[row * MAXBAND + p] = i;
      if (msk[i]) atomicAdd(&scsel, 1);
    }
  }
  __syncthreads();
  if (tid == 0) {
    g_bandcnt[row] = scnt < MAXBAND ? scnt : MAXBAND;
    g_bandsel[row] = scsel;
  }
}

// ---------------- refine: exact fp32 logits for band tokens ----------------
__global__ __launch_bounds__(256)
void refine_kernel(const float* __restrict__ X, const float* __restrict__ W1,
                   const float* __restrict__ b1, const float* __restrict__ W2) {
  const int jc = blockIdx.x, row = blockIdx.y, c0 = blockIdx.z * 16;
  const int cnt = g_bandcnt[row];
  if (c0 >= cnt) return;
  const int tid = threadIdx.x;
  const int tc = tid & 15, tj = tid >> 4;

  __shared__ int stok[16];
  __shared__ float Xs[16][33];
  __shared__ float Ws[32][132];
  __shared__ float part[16][17];

  if (tid < 16)
    stok[tid] = (c0 + tid < cnt) ? row * SEQ + g_band_idx[row * MAXBAND + c0 + tid]
                                 : row * SEQ;
  __syncthreads();

  float acc[8];
#pragma unroll
  for (int u = 0; u < 8; u++) acc[u] = 0.0f;

  for (int k0 = 0; k0 < DDIM; k0 += 32) {
#pragma unroll
    for (int p = 0; p < 2; p++) {
      int e = tid + p * 256;
      int c = e >> 5, kk = e & 31;
      Xs[c][kk] = X[(size_t)stok[c] * DDIM + k0 + kk];
    }
#pragma unroll
    for (int q = 0; q < 16; q++) {
      int f = tid + q * 256;
      int kk = f >> 7, jj = f & 127;
      Ws[kk][jj] = W1[(size_t)(k0 + kk) * HDIM + jc * 128 + jj];
    }
    __syncthreads();
#pragma unroll
    for (int kk = 0; kk < 32; kk++) {
      float x = Xs[tc][kk];
      const float4* wrow = (const float4*)&Ws[kk][tj * 8];
      float4 w0 = wrow[0], w1 = wrow[1];
      acc[0] = fmaf(x, w0.x, acc[0]); acc[1] = fmaf(x, w0.y, acc[1]);
      acc[2] = fmaf(x, w0.z, acc[2]); acc[3] = fmaf(x, w0.w, acc[3]);
      acc[4] = fmaf(x, w1.x, acc[4]); acc[5] = fmaf(x, w1.y, acc[5]);
      acc[6] = fmaf(x, w1.z, acc[6]); acc[7] = fmaf(x, w1.w, acc[7]);
    }
    __syncthreads();
  }

  float contrib = 0.0f;
#pragma unroll
  for (int u = 0; u < 8; u++) {
    int j = jc * 128 + tj * 8 + u;
    float h = acc[u] + b1[j];
    contrib += fmaxf(h, 0.0f) * W2[j];
  }
  part[tj][tc] = contrib;
  __syncthreads();
  if (tid < 16) {
    float s = 0.0f;
#pragma unroll
    for (int t = 0; t < 16; t++) s += part[t][tid];
    if (c0 + tid < cnt)
      g_band_partial[(row * MAXBAND + c0 + tid) * 16 + jc] = s;
  }
}

// ---------------- fixup: re-rank band by exact values ----------------
__global__ __launch_bounds__(64)
void fixup_kernel(float* __restrict__ out_mask, uint32_t r2k0, uint32_t r2k1) {
  const int row = blockIdx.x, t = threadIdx.x;
  const int cnt = g_bandcnt[row], csel = g_bandsel[row];
  __shared__ float sv[64], svv[64];
  __shared__ int si[64];

  float v = -INFINITY; int idx = -1;
  if (t < cnt) {
    idx = g_band_idx[row * MAXBAND + t];
    float s = 0.0f;
#pragma unroll
    for (int c = 0; c < 16; c++) s += g_band_partial[(row * MAXBAND + t) * 16 + c];
    v = s + gumbel_at(r2k0, r2k1, (uint32_t)(row * SEQ + idx));
  }
  svv[t] = v;
  __syncthreads();

  int chosen = 0;
  for (int it = 0; it < csel; it++) {
    sv[t] = svv[t]; si[t] = t;
    __syncthreads();
    for (int off = 32; off > 0; off >>= 1) {
      if (t < off) {
        if (sv[t + off] > sv[t] || (sv[t + off] == sv[t] && si[t + off] < si[t])) {
          sv[t] = sv[t + off]; si[t] = si[t + off];
        }
      }
      __syncthreads();
    }
    if (t == si[0]) { chosen = 1; svv[t] = -INFINITY; }
    __syncthreads();
  }

  if (t < cnt) {
    float m = (float)chosen;
    out_mask[row * SEQ + idx] = m;
    g_mask[row * SEQ + idx] = m;
  }
}

// ---------------- scatter ----------------
__global__ __launch_bounds__(256)
void scatter_kernel(const float* __restrict__ X, float* __restrict__ out) {
  const int t = blockIdx.x;
  const int tid = threadIdx.x;
  const float m = g_mask[t];
  float4* dst = (float4*)(out + (size_t)t * DDIM);
  if (m != 0.0f) {
    const float4* src = (const float4*)(X + (size_t)t * DDIM);
    dst[tid] = src[tid];
  } else {
    dst[tid] = make_float4(0.0f, 0.0f, 0.0f, 0.0f);
  }
}

// ---------------- launch ----------------
extern "C" void kernel_launch(void* const* d_in, const int* in_sizes, int n_in,
                              void* d_out, int out_size) {
  const float* X  = (const float*)d_in[0];
  const float* W1 = (const float*)d_in[1];
  const float* b1 = (const float*)d_in[2];
  const float* W2 = (const float*)d_in[3];
  const float* kl = (const float*)d_in[5];

  float* out = (float*)d_out;
  float* out_mask = out + (size_t)NTOK * DDIM;
  float* out_ek   = out_mask + NTOK;

  uint32_t r1k0, r1k1, r2k0, r2k1;
  tf2x32(0u, 42u, 0u, 0u, &r1k0, &r1k1);
  tf2x32(0u, 42u, 0u, 1u, &r2k0, &r2k1);

  cudaFuncSetAttribute(gemm_logits_kernel,
                       cudaFuncAttributeMaxDynamicSharedMemorySize, DYN_SMEM);

  convX_kernel<<<(NTOK * DDIM / 4) / 256, 256>>>(X);
  convW_kernel<<<dim3(HDIM / 32, DDIM / 32), 256>>>(W1);
  k_select_kernel<<<1, 64>>>(kl, out_ek, r1k0, r1k1);
  gemm_logits_kernel<<<(NTOK / BM) * NHC, 512, DYN_SMEM>>>(b1, W2);
  topk_kernel<<<BATCH, 1024>>>(out_mask, r2k0, r2k1);
  refine_kernel<<<dim3(16, BATCH, 4), 256>>>(X, W1, b1, W2);
  fixup_kernel<<<BATCH, 64>>>(out_mask, r2k0, r2k1);
  scatter_kernel<<<NTOK, 256>>>(X, out);
}

// round 14
// speedup vs baseline: 2.0178x; 1.0461x over previous
#include <cuda_runtime.h>
#include <cuda_bf16.h>
#include <stdint.h>
#include <math.h>

#define NTOK 32768
#define BATCH 8
#define SEQ 4096
#define DDIM 1024
#define HDIM 2048
#define MAXK 64

#define BM 128
#define BN 256
#define BK 64
#define NHC 8
#define UNIT_KSTAGES (DDIM / BK)    // 16

// smem: 3 stages of [A 128x144B = 18432][B 256x144B = 36864] = 55296 each
#define STAGE_BYTES 55296
#define NPIPE 3
#define B1S_OFF  (NPIPE * STAGE_BYTES)      // 165888
#define W2S_OFF  (B1S_OFF + 1024)
#define RED_OFF  (W2S_OFF + 1024)
#define DYN_SMEM (RED_OFF + 2048)           // 169984

#define BANDW  0.06f
#define MAXBAND 64

// ---------------- scratch ----------------
static __device__ float g_part[(size_t)NTOK * NHC];
static __device__ float g_mask[NTOK];
static __device__ int   g_ksel;
static __device__ __nv_bfloat16 g_Xhi[(size_t)NTOK * DDIM];
static __device__ __nv_bfloat16 g_Whi[(size_t)HDIM * DDIM];  // n-major (transposed)
static __device__ int   g_band_idx[BATCH * MAXBAND];
static __device__ float g_band_partial[BATCH * MAXBAND * 16];
static __device__ int   g_bandcnt[BATCH];
static __device__ int   g_bandsel[BATCH];

// ---------------- PTX helpers ----------------
__device__ __forceinline__ uint32_t smem_u32(const void* p) {
  uint32_t a;
  asm("{ .reg .u64 t; cvta.to.shared.u64 t, %1; cvt.u32.u64 %0, t; }" : "=r"(a) : "l"(p));
  return a;
}
__device__ __forceinline__ void cp16(uint32_t saddr, const void* gaddr) {
  asm volatile("cp.async.cg.shared.global [%0], [%1], 16;" :: "r"(saddr), "l"(gaddr));
}
#define CP_COMMIT() asm volatile("cp.async.commit_group;" ::: "memory")
#define CP_WAIT1()  asm volatile("cp.async.wait_group 1;" ::: "memory")
#define CP_WAIT0()  asm volatile("cp.async.wait_group 0;" ::: "memory")

__device__ __forceinline__ void ldsm4(uint32_t* r, uint32_t addr) {
  asm volatile("ldmatrix.sync.aligned.m8n8.x4.shared.b16 {%0,%1,%2,%3}, [%4];"
               : "=r"(r[0]), "=r"(r[1]), "=r"(r[2]), "=r"(r[3]) : "r"(addr));
}
__device__ __forceinline__ void ldsm_b2(uint32_t (*b)[2], uint32_t addr) {
  uint32_t r[4];
  ldsm4(r, addr);
  b[0][0] = r[0]; b[0][1] = r[2];
  b[1][0] = r[1]; b[1][1] = r[3];
}
__device__ __forceinline__ void mma16816(float* c, const uint32_t* a, const uint32_t* b) {
  asm volatile("mma.sync.aligned.m16n8k16.row.col.f32.bf16.bf16.f32 "
               "{%0,%1,%2,%3}, {%4,%5,%6,%7}, {%8,%9}, {%0,%1,%2,%3};"
               : "+f"(c[0]), "+f"(c[1]), "+f"(c[2]), "+f"(c[3])
               : "r"(a[0]), "r"(a[1]), "r"(a[2]), "r"(a[3]), "r"(b[0]), "r"(b[1]));
}

// monotone float->uint key (larger float -> larger key)
__device__ __forceinline__ uint32_t f2key(float f) {
  uint32_t b = __float_as_uint(f);
  return (b & 0x80000000u) ? ~b : (b | 0x80000000u);
}
__device__ __forceinline__ float key2f(uint32_t k) {
  uint32_t b = (k & 0x80000000u) ? (k & 0x7FFFFFFFu) : ~k;
  return __uint_as_float(b);
}

// ---------------- threefry2x32-20 (JAX) ----------------
__host__ __device__ __forceinline__ void tf2x32(uint32_t k0, uint32_t k1,
                                                uint32_t x0, uint32_t x1,
                                                uint32_t* o0, uint32_t* o1) {
  uint32_t ks2 = k0 ^ k1 ^ 0x1BD11BDAu;
#define ROTL(v, d) (((v) << (d)) | ((v) >> (32 - (d))))
#define RND(r) { x0 += x1; x1 = ROTL(x1, r); x1 ^= x0; }
  x0 += k0; x1 += k1;
  RND(13) RND(15) RND(26) RND(6)
  x0 += k1; x1 += ks2 + 1u;
  RND(17) RND(29) RND(16) RND(24)
  x0 += ks2; x1 += k0 + 2u;
  RND(13) RND(15) RND(26) RND(6)
  x0 += k0; x1 += k1 + 3u;
  RND(17) RND(29) RND(16) RND(24)
  x0 += k1; x1 += ks2 + 4u;
  RND(13) RND(15) RND(26) RND(6)
  x0 += ks2; x1 += k0 + 5u;
#undef RND
#undef ROTL
  *o0 = x0; *o1 = x1;
}
__device__ __forceinline__ float gumbel_at(uint32_t k0, uint32_t k1, uint32_t idx) {
  uint32_t a, b;
  tf2x32(k0, k1, 0u, idx, &a, &b);
  uint32_t bits = a ^ b;
  float u = __uint_as_float((bits >> 9) | 0x3f800000u) - 1.0f;
  u = u + 1e-8f;
  u = fmaxf(1e-8f, u);
  return -logf(-logf(u));
}

// ---------------- conversion kernels (hi only) ----------------
__global__ __launch_bounds__(256) void convX_kernel(const float* __restrict__ X) {
  size_t i = (size_t)blockIdx.x * 256 + threadIdx.x;   // float4 index
  float4 v = ((const float4*)X)[i];
  __nv_bfloat162* H = (__nv_bfloat162*)g_Xhi;
  H[i * 2]     = __nv_bfloat162(__float2bfloat16(v.x), __float2bfloat16(v.y));
  H[i * 2 + 1] = __nv_bfloat162(__float2bfloat16(v.z), __float2bfloat16(v.w));
}

__global__ __launch_bounds__(256) void convW_kernel(const float* __restrict__ W1) {
  __shared__ float s[32][33];
  int n0 = blockIdx.x * 32;
  int k0 = blockIdx.y * 32;
  int tx = threadIdx.x & 31, ty = threadIdx.x >> 5;   // ty 0..7
#pragma unroll
  for (int j = 0; j < 4; j++) {
    int k = k0 + ty + j * 8;
    s[ty + j * 8][tx] = W1[(size_t)k * HDIM + n0 + tx];
  }
  __syncthreads();
#pragma unroll
  for (int j = 0; j < 4; j++) {
    int n = n0 + ty + j * 8;
    g_Whi[(size_t)n * DDIM + k0 + tx] = __float2bfloat16(s[tx][ty + j * 8]);
  }
}

// ---------------- k-select ----------------
__global__ void k_select_kernel(const float* __restrict__ k_logits,
                                float* __restrict__ out_ek,
                                uint32_t r1k0, uint32_t r1k1) {
  __shared__ float z[MAXK];
  int t = threadIdx.x;
  if (t < MAXK) z[t] = k_logits[t] + gumbel_at(r1k0, r1k1, (uint32_t)t);
  __syncthreads();
  if (t == 0) {
    float m = -INFINITY; int am = 0;
    for (int i = 0; i < MAXK; i++) if (z[i] > m) { m = z[i]; am = i; }
    float s = 0.0f, e[MAXK];
    for (int i = 0; i < MAXK; i++) { e[i] = expf(z[i] - m); s += e[i]; }
    float ek = 0.0f;
    for (int i = 0; i < MAXK; i++) ek += (e[i] / s) * (float)(i + 1);
    out_ek[0] = ek;
    g_ksel = am + 1;
  }
}

// ---------------- 1-pass bf16 HMMA GEMM -> per-chunk partial logits ----------------
// grid = 2048 units (256 row-blocks x 8 h-chunks), 512 threads, warp tile 32x64.
__global__ __launch_bounds__(512, 1)
void gemm_logits_kernel(const float* __restrict__ b1, const float* __restrict__ W2) {
  extern __shared__ char smem[];
  const uint32_t sb = smem_u32(smem);
  const int tid = threadIdx.x;
  const int lane = tid & 31;
  const int wid = tid >> 5;
  const int wm = wid & 3;           // 0..3 (m, 32-row slices)
  const int wn = wid >> 2;          // 0..3 (n, 64-col slices)
  const int row0 = (blockIdx.x >> 3) * BM;
  const int hc = blockIdx.x & 7;

  float* b1s = (float*)(smem + B1S_OFF);
  float* w2s = (float*)(smem + W2S_OFF);
  float* red = (float*)(smem + RED_OFF);

  // loader: A 1024 chunks (2/thread), B 2048 chunks (4/thread); 16B chunks
  const int cr = tid >> 3, ch = tid & 7;   // row 0..63 base, 16B-half 0..7
  const char* pXb = (const char*)g_Xhi + (((size_t)(row0 + cr)) << 11) + ch * 16;
  const char* pWb = (const char*)g_Whi + (((size_t)(hc * BN + cr)) << 11) + ch * 16;
  const uint32_t sA = (uint32_t)(cr * 144 + ch * 16);

#define ISSUE_STAGE(stgbase, ks) do {                                        \
    const uint32_t _stg = (stgbase);                                         \
    const size_t _ko = ((size_t)(ks)) << 7;                                  \
    cp16(_stg + sA,                  pXb + _ko);                             \
    cp16(_stg + sA + 9216,           pXb + (64ull << 11) + _ko);             \
    cp16(_stg + 18432 + sA,          pWb + _ko);                             \
    cp16(_stg + 18432 + sA + 9216,   pWb + (64ull << 11) + _ko);             \
    cp16(_stg + 18432 + sA + 18432,  pWb + (128ull << 11) + _ko);            \
    cp16(_stg + 18432 + sA + 27648,  pWb + (192ull << 11) + _ko);            \
  } while (0)

  // prefetch 2 stages
  ISSUE_STAGE(sb, 0);
  CP_COMMIT();
  ISSUE_STAGE(sb + STAGE_BYTES, 1);
  CP_COMMIT();

  // stage this chunk's b1/W2 (256 floats each); published by loop barrier
  if (tid < 256) {
    b1s[tid] = b1[hc * BN + tid];
    w2s[tid] = W2[hc * BN + tid];
  }

  float C[2][8][4];
#pragma unroll
  for (int mi = 0; mi < 2; mi++)
#pragma unroll
    for (int ni = 0; ni < 8; ni++)
#pragma unroll
      for (int j = 0; j < 4; j++) C[mi][ni][j] = 0.0f;

  const int lr = lane & 15, lh = lane >> 4;
  const uint32_t aOff = (uint32_t)((wm * 32 + lr) * 144 + lh * 16);
  const uint32_t bOff = (uint32_t)(18432 + (wn * 64 + lr) * 144 + lh * 16);

  int buf = 0;
  for (int s = 0; s < UNIT_KSTAGES; s++) {
    if (s + 2 < UNIT_KSTAGES) CP_WAIT1(); else CP_WAIT0();
    __syncthreads();   // publish buf s; certify compute(s-1) done
    if (s + 2 < UNIT_KSTAGES) {
      int b2i = buf + 2; if (b2i >= NPIPE) b2i -= NPIPE;
      ISSUE_STAGE(sb + b2i * STAGE_BYTES, s + 2);
      CP_COMMIT();
    }

    const uint32_t aB = sb + buf * STAGE_BYTES + aOff;
    const uint32_t bB = sb + buf * STAGE_BYTES + bOff;
#pragma unroll
    for (int k16 = 0; k16 < 4; k16++) {
      const uint32_t kofs = (uint32_t)(k16 * 32);
      uint32_t ah[2][4], bb0[4][2], bb1[4][2];
      ldsm4(ah[0], aB + kofs);
      ldsm4(ah[1], aB + 16 * 144 + kofs);
      ldsm_b2(bb0 + 0, bB + kofs);
      ldsm_b2(bb0 + 2, bB + 16 * 144 + kofs);
      ldsm_b2(bb1 + 0, bB + 2 * (16 * 144) + kofs);
      ldsm_b2(bb1 + 2, bB + 3 * (16 * 144) + kofs);
#pragma unroll
      for (int mi = 0; mi < 2; mi++)
#pragma unroll
        for (int ni = 0; ni < 4; ni++) mma16816(C[mi][ni], ah[mi], bb0[ni]);
#pragma unroll
      for (int mi = 0; mi < 2; mi++)
#pragma unroll
        for (int ni = 0; ni < 4; ni++) mma16816(C[mi][ni + 4], ah[mi], bb1[ni]);
    }
    buf++; if (buf == NPIPE) buf = 0;
  }

  // epilogue: bias -> relu -> *W2 -> per-row partial for this h-chunk
  float lacc[4] = {0.0f, 0.0f, 0.0f, 0.0f};
  const int colbase = wn * 64 + (lane & 3) * 2;
#pragma unroll
  for (int ni = 0; ni < 8; ni++) {
    const int c0 = colbase + ni * 8;
    const float b10 = b1s[c0], b11 = b1s[c0 + 1];
    const float w20 = w2s[c0], w21 = w2s[c0 + 1];
#pragma unroll
    for (int mi = 0; mi < 2; mi++) {
      lacc[mi * 2 + 0] += fmaxf(C[mi][ni][0] + b10, 0.0f) * w20
                        + fmaxf(C[mi][ni][1] + b11, 0.0f) * w21;
      lacc[mi * 2 + 1] += fmaxf(C[mi][ni][2] + b10, 0.0f) * w20
                        + fmaxf(C[mi][ni][3] + b11, 0.0f) * w21;
    }
  }
#pragma unroll
  for (int j = 0; j < 4; j++) {
    lacc[j] += __shfl_xor_sync(0xFFFFFFFFu, lacc[j], 1);
    lacc[j] += __shfl_xor_sync(0xFFFFFFFFu, lacc[j], 2);
  }
  __syncthreads();
  if ((lane & 3) == 0) {
    const int r = lane >> 2;
    red[wn * 128 + wm * 32 + r]      = lacc[0];
    red[wn * 128 + wm * 32 + 8 + r]  = lacc[1];
    red[wn * 128 + wm * 32 + 16 + r] = lacc[2];
    red[wn * 128 + wm * 32 + 24 + r] = lacc[3];
  }
  __syncthreads();
  if (tid < BM)
    g_part[(size_t)(row0 + tid) * NHC + hc] =
        (red[tid] + red[128 + tid]) + (red[256 + tid] + red[384 + tid]);
}

// ---------------- top-k via 4-round radix select + band extraction ----------------
__global__ __launch_bounds__(1024)
void topk_kernel(float* __restrict__ out_mask, uint32_t r2k0, uint32_t r2k1) {
  __shared__ float vals[SEQ];
  __shared__ unsigned char msk[SEQ];
  __shared__ int hist[256];
  __shared__ int s_digit, s_acc;
  __shared__ int tieIdx[64];
  __shared__ int tieCnt;
  __shared__ int scnt, scsel;
  const int row = blockIdx.x;
  const int tid = threadIdx.x;

#pragma unroll
  for (int j = 0; j < 4; j++) {
    int i = tid + j * 1024;
    uint32_t idx = (uint32_t)(row * SEQ + i);
    const float4* pp = (const float4*)&g_part[(size_t)idx * NHC];
    float4 a = pp[0], b = pp[1];
    float s = ((a.x + a.y) + (a.z + a.w)) + ((b.x + b.y) + (b.z + b.w));
    vals[i] = s + gumbel_at(r2k0, r2k1, idx);
    msk[i] = 0;
  }
  if (tid == 0) { scnt = 0; scsel = 0; tieCnt = 0; }
  __syncthreads();

  const int k = g_ksel;
  // 4-round MSB radix select for the k-th largest key
  uint32_t prefix = 0;
  int kk = k;
  for (int shift = 24; shift >= 0; shift -= 8) {
    if (tid < 256) hist[tid] = 0;
    __syncthreads();
    const uint32_t pmask = (shift == 24) ? 0u : (0xFFFFFFFFu << (shift + 8));
#pragma unroll
    for (int j = 0; j < 4; j++) {
      uint32_t key = f2key(vals[tid + j * 1024]);
      if ((key & pmask) == prefix) atomicAdd(&hist[(key >> shift) & 0xFF], 1);
    }
    __syncthreads();
    if (tid == 0) {
      int acc = 0, d = 255;
      for (; d > 0; d--) {
        if (acc + hist[d] >= kk) break;
        acc += hist[d];
      }
      s_digit = d; s_acc = acc;
    }
    __syncthreads();
    kk -= s_acc;
    prefix |= ((uint32_t)s_digit) << shift;
    __syncthreads();
  }
  const uint32_t thKey = prefix;     // key of the k-th largest value
  const float sAk = key2f(thKey);

  // mark strict winners; collect ties (== threshold key)
#pragma unroll
  for (int j = 0; j < 4; j++) {
    int i = tid + j * 1024;
    uint32_t key = f2key(vals[i]);
    if (key > thKey) msk[i] = 1;
    else if (key == thKey) {
      int p = atomicAdd(&tieCnt, 1);
      if (p < 64) tieIdx[p] = i;
    }
  }
  __syncthreads();
  if (tid == 0) {
    // select lowest-index kk ties (normally 1 tie, kk == 1)
    int tc = tieCnt < 64 ? tieCnt : 64;
    for (int sel = 0; sel < kk; sel++) {
      int best = SEQ, bp = -1;
      for (int p = 0; p < tc; p++)
        if (tieIdx[p] < best) { best = tieIdx[p]; bp = p; }
      if (bp >= 0) { msk[best] = 1; tieIdx[bp] = SEQ; }
    }
  }
  __syncthreads();

  // write masks + band capture
#pragma unroll
  for (int j = 0; j < 4; j++) {
    int i = tid + j * 1024;
    float m = (float)msk[i];
    out_mask[row * SEQ + i] = m;
    g_mask[row * SEQ + i] = m;
    if (fabsf(vals[i] - sAk) <= BANDW) {
      int p = atomicAdd(&scnt, 1);
      if (p < MAXBAND) g_band_idx[row * MAXBAND + p] = i;
      if (msk[i]) atomicAdd(&scsel, 1);
    }
  }
  __syncthreads();
  if (tid == 0) {
    g_bandcnt[row] = scnt < MAXBAND ? scnt : MAXBAND;
    g_bandsel[row] = scsel;
  }
}

// ---------------- refine: exact fp32 logits for band tokens ----------------
__global__ __launch_bounds__(256)
void refine_kernel(const float* __restrict__ X, const float* __restrict__ W1,
                   const float* __restrict__ b1, const float* __restrict__ W2) {
  const int jc = blockIdx.x, row = blockIdx.y, c0 = blockIdx.z * 16;
  const int cnt = g_bandcnt[row];
  if (c0 >= cnt) return;
  const int tid = threadIdx.x;
  const int tc = tid & 15, tj = tid >> 4;

  __shared__ int stok[16];
  __shared__ float Xs[16][33];
  __shared__ float Ws[32][132];
  __shared__ float part[16][17];

  if (tid < 16)
    stok[tid] = (c0 + tid < cnt) ? row * SEQ + g_band_idx[row * MAXBAND + c0 + tid]
                                 : row * SEQ;
  __syncthreads();

  float acc[8];
#pragma unroll
  for (int u = 0; u < 8; u++) acc[u] = 0.0f;

  for (int k0 = 0; k0 < DDIM; k0 += 32) {
#pragma unroll
    for (int p = 0; p < 2; p++) {
      int e = tid + p * 256;
      int c = e >> 5, kk = e & 31;
      Xs[c][kk] = X[(size_t)stok[c] * DDIM + k0 + kk];
    }
#pragma unroll
    for (int q = 0; q < 16; q++) {
      int f = tid + q * 256;
      int kk = f >> 7, jj = f & 127;
      Ws[kk][jj] = W1[(size_t)(k0 + kk) * HDIM + jc * 128 + jj];
    }
    __syncthreads();
#pragma unroll
    for (int kk = 0; kk < 32; kk++) {
      float x = Xs[tc][kk];
      const float4* wrow = (const float4*)&Ws[kk][tj * 8];
      float4 w0 = wrow[0], w1 = wrow[1];
      acc[0] = fmaf(x, w0.x, acc[0]); acc[1] = fmaf(x, w0.y, acc[1]);
      acc[2] = fmaf(x, w0.z, acc[2]); acc[3] = fmaf(x, w0.w, acc[3]);
      acc[4] = fmaf(x, w1.x, acc[4]); acc[5] = fmaf(x, w1.y, acc[5]);
      acc[6] = fmaf(x, w1.z, acc[6]); acc[7] = fmaf(x, w1.w, acc[7]);
    }
    __syncthreads();
  }

  float contrib = 0.0f;
#pragma unroll
  for (int u = 0; u < 8; u++) {
    int j = jc * 128 + tj * 8 + u;
    float h = acc[u] + b1[j];
    contrib += fmaxf(h, 0.0f) * W2[j];
  }
  part[tj][tc] = contrib;
  __syncthreads();
  if (tid < 16) {
    float s = 0.0f;
#pragma unroll
    for (int t = 0; t < 16; t++) s += part[t][tid];
    if (c0 + tid < cnt)
      g_band_partial[(row * MAXBAND + c0 + tid) * 16 + jc] = s;
  }
}

// ---------------- fixup: re-rank band by exact values ----------------
__global__ __launch_bounds__(64)
void fixup_kernel(float* __restrict__ out_mask, uint32_t r2k0, uint32_t r2k1) {
  const int row = blockIdx.x, t = threadIdx.x;
  const int cnt = g_bandcnt[row], csel = g_bandsel[row];
  __shared__ float sv[64], svv[64];
  __shared__ int si[64];

  float v = -INFINITY; int idx = -1;
  if (t < cnt) {
    idx = g_band_idx[row * MAXBAND + t];
    float s = 0.0f;
#pragma unroll
    for (int c = 0; c < 16; c++) s += g_band_partial[(row * MAXBAND + t) * 16 + c];
    v = s + gumbel_at(r2k0, r2k1, (uint32_t)(row * SEQ + idx));
  }
  svv[t] = v;
  __syncthreads();

  int chosen = 0;
  for (int it = 0; it < csel; it++) {
    sv[t] = svv[t]; si[t] = t;
    __syncthreads();
    for (int off = 32; off > 0; off >>= 1) {
      if (t < off) {
        if (sv[t + off] > sv[t] || (sv[t + off] == sv[t] && si[t + off] < si[t])) {
          sv[t] = sv[t + off]; si[t] = si[t + off];
        }
      }
      __syncthreads();
    }
    if (t == si[0]) { chosen = 1; svv[t] = -INFINITY; }
    __syncthreads();
  }

  if (t < cnt) {
    float m = (float)chosen;
    out_mask[row * SEQ + idx] = m;
    g_mask[row * SEQ + idx] = m;
  }
}

// ---------------- scatter ----------------
__global__ __launch_bounds__(256)
void scatter_kernel(const float* __restrict__ X, float* __restrict__ out) {
  const int t = blockIdx.x;
  const int tid = threadIdx.x;
  const float m = g_mask[t];
  float4* dst = (float4*)(out + (size_t)t * DDIM);
  if (m != 0.0f) {
    const float4* src = (const float4*)(X + (size_t)t * DDIM);
    dst[tid] = src[tid];
  } else {
    dst[tid] = make_float4(0.0f, 0.0f, 0.0f, 0.0f);
  }
}

// ---------------- launch ----------------
extern "C" void kernel_launch(void* const* d_in, const int* in_sizes, int n_in,
                              void* d_out, int out_size) {
  const float* X  = (const float*)d_in[0];
  const float* W1 = (const float*)d_in[1];
  const float* b1 = (const float*)d_in[2];
  const float* W2 = (const float*)d_in[3];
  const float* kl = (const float*)d_in[5];

  float* out = (float*)d_out;
  float* out_mask = out + (size_t)NTOK * DDIM;
  float* out_ek   = out_mask + NTOK;

  uint32_t r1k0, r1k1, r2k0, r2k1;
  tf2x32(0u, 42u, 0u, 0u, &r1k0, &r1k1);
  tf2x32(0u, 42u, 0u, 1u, &r2k0, &r2k1);

  cudaFuncSetAttribute(gemm_logits_kernel,
                       cudaFuncAttributeMaxDynamicSharedMemorySize, DYN_SMEM);

  convX_kernel<<<(NTOK * DDIM / 4) / 256, 256>>>(X);
  convW_kernel<<<dim3(HDIM / 32, DDIM / 32), 256>>>(W1);
  k_select_kernel<<<1, 64>>>(kl, out_ek, r1k0, r1k1);
  gemm_logits_kernel<<<(NTOK / BM) * NHC, 512, DYN_SMEM>>>(b1, W2);
  topk_kernel<<<BATCH, 1024>>>(out_mask, r2k0, r2k1);
  refine_kernel<<<dim3(16, BATCH, 4), 256>>>(X, W1, b1, W2);
  fixup_kernel<<<BATCH, 64>>>(out_mask, r2k0, r2k1);
  scatter_kernel<<<NTOK, 256>>>(X, out);
}